// round 1
// baseline (speedup 1.0000x reference)
#include <cuda_runtime.h>
#include <math.h>

#define SEQ   2048
#define BATCH 4
#define EMB   1024
#define NHEAD 16
#define HDIM  64
#define ROWS  (BATCH * SEQ)

// scratch (allocation-free contract: __device__ globals)
__device__ float g_Q[ROWS * EMB];
__device__ float g_K[ROWS * EMB];
__device__ float g_V[ROWS * EMB];
__device__ float g_A[ROWS * EMB];

// ---------------------------------------------------------------------------
// GEMM: C[M,N] = A[M,K] @ W[K,N] + bias,  M=8192, N=K=1024
// 128x128 block tile, Ktile=16, 256 threads, 8x8 per thread, double-buffered.
// ---------------------------------------------------------------------------
__global__ __launch_bounds__(256) void gemm_bias_kernel(
    const float* __restrict__ A, const float* __restrict__ W,
    const float* __restrict__ bias, float* __restrict__ C)
{
    __shared__ float As[2][16][128];   // transposed: As[k][m]
    __shared__ float Ws[2][16][128];   // Ws[k][n]

    const int t    = threadIdx.x;
    const int tm   = t >> 4;           // 0..15 (m direction)
    const int tn   = t & 15;           // 0..15 (n direction)
    const int row0 = blockIdx.y * 128;
    const int col0 = blockIdx.x * 128;

    // global-load assignment
    const int ar = t >> 1;             // A row in tile (0..127)
    const int ac = (t & 1) * 8;        // A col base within ktile (0 or 8)
    const int wr = t >> 4;             // W row in ktile (0..15)
    const int wc = (t & 15) * 8;       // W col base (0..120)

    float acc[8][8];
#pragma unroll
    for (int i = 0; i < 8; i++)
#pragma unroll
        for (int j = 0; j < 8; j++) acc[i][j] = 0.f;

    // prologue prefetch (k0 = 0)
    float4 a0 = *(const float4*)(A + (size_t)(row0 + ar) * EMB + ac);
    float4 a1 = *(const float4*)(A + (size_t)(row0 + ar) * EMB + ac + 4);
    float4 w0 = *(const float4*)(W + (size_t)wr * EMB + col0 + wc);
    float4 w1 = *(const float4*)(W + (size_t)wr * EMB + col0 + wc + 4);

    const int NKT = EMB / 16;
    for (int kt = 0; kt < NKT; kt++) {
        const int buf = kt & 1;
        As[buf][ac + 0][ar] = a0.x; As[buf][ac + 1][ar] = a0.y;
        As[buf][ac + 2][ar] = a0.z; As[buf][ac + 3][ar] = a0.w;
        As[buf][ac + 4][ar] = a1.x; As[buf][ac + 5][ar] = a1.y;
        As[buf][ac + 6][ar] = a1.z; As[buf][ac + 7][ar] = a1.w;
        *(float4*)&Ws[buf][wr][wc]     = w0;
        *(float4*)&Ws[buf][wr][wc + 4] = w1;
        __syncthreads();

        if (kt + 1 < NKT) {
            const int k0 = (kt + 1) * 16;
            a0 = *(const float4*)(A + (size_t)(row0 + ar) * EMB + k0 + ac);
            a1 = *(const float4*)(A + (size_t)(row0 + ar) * EMB + k0 + ac + 4);
            w0 = *(const float4*)(W + (size_t)(k0 + wr) * EMB + col0 + wc);
            w1 = *(const float4*)(W + (size_t)(k0 + wr) * EMB + col0 + wc + 4);
        }

#pragma unroll
        for (int kk = 0; kk < 16; kk++) {
            float a[8], w[8];
            *(float4*)(a)     = *(const float4*)&As[buf][kk][tm * 8];
            *(float4*)(a + 4) = *(const float4*)&As[buf][kk][tm * 8 + 4];
            *(float4*)(w)     = *(const float4*)&Ws[buf][kk][tn * 8];
            *(float4*)(w + 4) = *(const float4*)&Ws[buf][kk][tn * 8 + 4];
#pragma unroll
            for (int i = 0; i < 8; i++)
#pragma unroll
                for (int j = 0; j < 8; j++)
                    acc[i][j] += a[i] * w[j];
        }
        // single sync per iter is safe with double buffering:
        // next iteration's store targets buf^1, whose last readers finished
        // before the barrier this iteration.
    }

#pragma unroll
    for (int i = 0; i < 8; i++) {
        const int r = row0 + tm * 8 + i;
#pragma unroll
        for (int j4 = 0; j4 < 2; j4++) {
            const int c = col0 + tn * 8 + j4 * 4;
            const float4 bv = *(const float4*)(bias + c);
            float4 o;
            o.x = acc[i][j4 * 4 + 0] + bv.x;
            o.y = acc[i][j4 * 4 + 1] + bv.y;
            o.z = acc[i][j4 * 4 + 2] + bv.z;
            o.w = acc[i][j4 * 4 + 3] + bv.w;
            *(float4*)(C + (size_t)r * EMB + c) = o;
        }
    }
}

// ---------------------------------------------------------------------------
// Flash attention, fp32. One block = (batch b, head h, 64 query rows).
// Q/K stored [d][row] in smem with XOR swizzle (phys col group = (row>>2)^(d>>2))
// so both GEMM stages read conflict-free LDS.128.
// scores = (q . k) * 8  (reference multiplies by sqrt(d))
// ---------------------------------------------------------------------------
__global__ __launch_bounds__(256) void flash_kernel(
    const float* __restrict__ Q, const float* __restrict__ K,
    const float* __restrict__ V, float* __restrict__ O)
{
    extern __shared__ float smem[];
    float (*Qt)[64] = (float(*)[64])(smem);             // [d][i] swizzled
    float (*Kt)[64] = (float(*)[64])(smem + 64 * 64);   // [d][j] swizzled
    float (*Vs)[64] = (float(*)[64])(smem + 2 * 64 * 64); // [j][d] natural
    float (*Pt)[64] = (float(*)[64])(smem + 3 * 64 * 64); // [j][i] swizzled

    const int t  = threadIdx.x;
    const int tm = t >> 4;   // 0..15: owns rows i = tm*4..tm*4+3
    const int tn = t & 15;   // 0..15: owns cols j (or d) = tn*4..tn*4+3
    const int qt = blockIdx.x;
    const int h  = blockIdx.y;
    const int b  = blockIdx.z;
    const size_t base = (size_t)b * SEQ * EMB + (size_t)h * HDIM;

    // load Q tile (64 rows x 64 d), transpose + swizzle into Qt
#pragma unroll
    for (int i = 0; i < 4; i++) {
        const int f  = t + i * 256;
        const int r  = f >> 4;
        const int c4 = f & 15;
        const float4 v = *(const float4*)(Q + base + (size_t)(qt * 64 + r) * EMB + c4 * 4);
        const int pc = ((((r >> 2) ^ c4) & 15) << 2) | (r & 3);
        Qt[c4 * 4 + 0][pc] = v.x;
        Qt[c4 * 4 + 1][pc] = v.y;
        Qt[c4 * 4 + 2][pc] = v.z;
        Qt[c4 * 4 + 3][pc] = v.w;
    }

    float m_i[4], l_i[4], acc[4][4];
#pragma unroll
    for (int i = 0; i < 4; i++) {
        m_i[i] = -1e30f;
        l_i[i] = 0.f;
#pragma unroll
        for (int j = 0; j < 4; j++) acc[i][j] = 0.f;
    }

    for (int kt = 0; kt < SEQ / 64; kt++) {
        __syncthreads();   // protect Kt/Vs/Pt from previous iteration readers
#pragma unroll
        for (int i = 0; i < 4; i++) {
            const int f  = t + i * 256;
            const int r  = f >> 4;
            const int c4 = f & 15;
            const size_t g = base + (size_t)(kt * 64 + r) * EMB + c4 * 4;
            const float4 kv = *(const float4*)(K + g);
            const int pc = ((((r >> 2) ^ c4) & 15) << 2) | (r & 3);
            Kt[c4 * 4 + 0][pc] = kv.x;
            Kt[c4 * 4 + 1][pc] = kv.y;
            Kt[c4 * 4 + 2][pc] = kv.z;
            Kt[c4 * 4 + 3][pc] = kv.w;
            *(float4*)&Vs[r][c4 * 4] = *(const float4*)(V + g);
        }
        __syncthreads();

        // S = Q K^T for this 64x64 tile
        float s[4][4];
#pragma unroll
        for (int i = 0; i < 4; i++)
#pragma unroll
            for (int j = 0; j < 4; j++) s[i][j] = 0.f;

#pragma unroll 16
        for (int d = 0; d < HDIM; d++) {
            const int dg = d >> 2;
            const float4 qv = *(const float4*)&Qt[d][(tm ^ dg) << 2];
            const float4 kv = *(const float4*)&Kt[d][(tn ^ dg) << 2];
            const float qa[4] = {qv.x, qv.y, qv.z, qv.w};
            const float ka[4] = {kv.x, kv.y, kv.z, kv.w};
#pragma unroll
            for (int i = 0; i < 4; i++)
#pragma unroll
                for (int j = 0; j < 4; j++)
                    s[i][j] += qa[i] * ka[j];
        }

        // online softmax (reference scale: multiply by sqrt(64) = 8)
#pragma unroll
        for (int i = 0; i < 4; i++) {
#pragma unroll
            for (int j = 0; j < 4; j++) s[i][j] *= 8.f;

            float mt = fmaxf(fmaxf(s[i][0], s[i][1]), fmaxf(s[i][2], s[i][3]));
#pragma unroll
            for (int off = 1; off < 16; off <<= 1)
                mt = fmaxf(mt, __shfl_xor_sync(0xffffffffu, mt, off));

            const float mnew = fmaxf(m_i[i], mt);
            const float corr = __expf(m_i[i] - mnew);
            m_i[i] = mnew;

            float p[4], rs = 0.f;
#pragma unroll
            for (int j = 0; j < 4; j++) {
                p[j] = __expf(s[i][j] - mnew);
                rs += p[j];
            }
#pragma unroll
            for (int off = 1; off < 16; off <<= 1)
                rs += __shfl_xor_sync(0xffffffffu, rs, off);

            l_i[i] = l_i[i] * corr + rs;
#pragma unroll
            for (int j = 0; j < 4; j++) acc[i][j] *= corr;

            // store P transposed+swizzled: Pt[j][i_global], phys col = (tm^tn)*4 + i
            const int pc = ((tm ^ tn) << 2) | i;
#pragma unroll
            for (int j = 0; j < 4; j++) Pt[tn * 4 + j][pc] = p[j];
        }
        __syncthreads();

        // O += P V  (thread owns rows i=tm*4.., dims d=tn*4..)
#pragma unroll 8
        for (int j = 0; j < 64; j++) {
            const float4 pv = *(const float4*)&Pt[j][(tm ^ (j >> 2)) << 2];
            const float4 vv = *(const float4*)&Vs[j][tn * 4];
            const float pa[4] = {pv.x, pv.y, pv.z, pv.w};
            const float va[4] = {vv.x, vv.y, vv.z, vv.w};
#pragma unroll
            for (int i = 0; i < 4; i++)
#pragma unroll
                for (int c = 0; c < 4; c++)
                    acc[i][c] += pa[i] * va[c];
        }
    }

    // epilogue: divide by l, write out in [b, s, h*D+d] layout
#pragma unroll
    for (int i = 0; i < 4; i++) {
        const float inv = 1.f / l_i[i];
        float4 o;
        o.x = acc[i][0] * inv;
        o.y = acc[i][1] * inv;
        o.z = acc[i][2] * inv;
        o.w = acc[i][3] * inv;
        *(float4*)(O + base + (size_t)(qt * 64 + tm * 4 + i) * EMB + tn * 4) = o;
    }
}

// ---------------------------------------------------------------------------
extern "C" void kernel_launch(void* const* d_in, const int* in_sizes, int n_in,
                              void* d_out, int out_size)
{
    const float* x  = (const float*)d_in[0];
    const float* Wq = (const float*)d_in[1];
    const float* bq = (const float*)d_in[2];
    const float* Wk = (const float*)d_in[3];
    const float* bk = (const float*)d_in[4];
    const float* Wv = (const float*)d_in[5];
    const float* bv = (const float*)d_in[6];
    const float* Wo = (const float*)d_in[7];
    const float* bo = (const float*)d_in[8];
    float* out = (float*)d_out;

    static float *Qp = nullptr, *Kp = nullptr, *Vp = nullptr, *Ap = nullptr;
    if (!Qp) {
        cudaGetSymbolAddress((void**)&Qp, g_Q);
        cudaGetSymbolAddress((void**)&Kp, g_K);
        cudaGetSymbolAddress((void**)&Vp, g_V);
        cudaGetSymbolAddress((void**)&Ap, g_A);
        cudaFuncSetAttribute(flash_kernel,
                             cudaFuncAttributeMaxDynamicSharedMemorySize,
                             4 * 64 * 64 * (int)sizeof(float));
    }

    const dim3 gg(EMB / 128, ROWS / 128);
    gemm_bias_kernel<<<gg, 256>>>(x, Wq, bq, Qp);
    gemm_bias_kernel<<<gg, 256>>>(x, Wk, bk, Kp);
    gemm_bias_kernel<<<gg, 256>>>(x, Wv, bv, Vp);

    const size_t smem = 4 * 64 * 64 * sizeof(float);
    flash_kernel<<<dim3(SEQ / 64, NHEAD, BATCH), 256, smem>>>(Qp, Kp, Vp, Ap);

    gemm_bias_kernel<<<gg, 256>>>(Ap, Wo, bo, out);
}

// round 2
// speedup vs baseline: 1.0001x; 1.0001x over previous
#include <cuda_runtime.h>
#include <math.h>

#define SEQ   2048
#define BATCH 4
#define EMB   1024
#define NHEAD 16
#define HDIM  64
#define ROWS  (BATCH * SEQ)

// scratch (allocation-free contract: __device__ globals)
__device__ float g_Q[ROWS * EMB];
__device__ float g_K[ROWS * EMB];
__device__ float g_V[ROWS * EMB];
__device__ float g_A[ROWS * EMB];

// ---------------------------------------------------------------------------
// GEMM: C[M,N] = A[M,K] @ W[K,N] + bias,  M=8192, N=K=1024
// 128x128 block tile, Ktile=16, 256 threads, 8x8 per thread, double-buffered.
// ---------------------------------------------------------------------------
__global__ __launch_bounds__(256) void gemm_bias_kernel(
    const float* __restrict__ A, const float* __restrict__ W,
    const float* __restrict__ bias, float* __restrict__ C)
{
    __shared__ float As[2][16][128];   // transposed: As[k][m]
    __shared__ float Ws[2][16][128];   // Ws[k][n]

    const int t    = threadIdx.x;
    const int tm   = t >> 4;           // 0..15 (m direction)
    const int tn   = t & 15;           // 0..15 (n direction)
    const int row0 = blockIdx.y * 128;
    const int col0 = blockIdx.x * 128;

    // global-load assignment
    const int ar = t >> 1;             // A row in tile (0..127)
    const int ac = (t & 1) * 8;        // A col base within ktile (0 or 8)
    const int wr = t >> 4;             // W row in ktile (0..15)
    const int wc = (t & 15) * 8;       // W col base (0..120)

    float acc[8][8];
#pragma unroll
    for (int i = 0; i < 8; i++)
#pragma unroll
        for (int j = 0; j < 8; j++) acc[i][j] = 0.f;

    // prologue prefetch (k0 = 0)
    float4 a0 = *(const float4*)(A + (size_t)(row0 + ar) * EMB + ac);
    float4 a1 = *(const float4*)(A + (size_t)(row0 + ar) * EMB + ac + 4);
    float4 w0 = *(const float4*)(W + (size_t)wr * EMB + col0 + wc);
    float4 w1 = *(const float4*)(W + (size_t)wr * EMB + col0 + wc + 4);

    const int NKT = EMB / 16;
    for (int kt = 0; kt < NKT; kt++) {
        const int buf = kt & 1;
        As[buf][ac + 0][ar] = a0.x; As[buf][ac + 1][ar] = a0.y;
        As[buf][ac + 2][ar] = a0.z; As[buf][ac + 3][ar] = a0.w;
        As[buf][ac + 4][ar] = a1.x; As[buf][ac + 5][ar] = a1.y;
        As[buf][ac + 6][ar] = a1.z; As[buf][ac + 7][ar] = a1.w;
        *(float4*)&Ws[buf][wr][wc]     = w0;
        *(float4*)&Ws[buf][wr][wc + 4] = w1;
        __syncthreads();

        if (kt + 1 < NKT) {
            const int k0 = (kt + 1) * 16;
            a0 = *(const float4*)(A + (size_t)(row0 + ar) * EMB + k0 + ac);
            a1 = *(const float4*)(A + (size_t)(row0 + ar) * EMB + k0 + ac + 4);
            w0 = *(const float4*)(W + (size_t)(k0 + wr) * EMB + col0 + wc);
            w1 = *(const float4*)(W + (size_t)(k0 + wr) * EMB + col0 + wc + 4);
        }

#pragma unroll
        for (int kk = 0; kk < 16; kk++) {
            float a[8], w[8];
            *(float4*)(a)     = *(const float4*)&As[buf][kk][tm * 8];
            *(float4*)(a + 4) = *(const float4*)&As[buf][kk][tm * 8 + 4];
            *(float4*)(w)     = *(const float4*)&Ws[buf][kk][tn * 8];
            *(float4*)(w + 4) = *(const float4*)&Ws[buf][kk][tn * 8 + 4];
#pragma unroll
            for (int i = 0; i < 8; i++)
#pragma unroll
                for (int j = 0; j < 8; j++)
                    acc[i][j] += a[i] * w[j];
        }
        // single sync per iter is safe with double buffering:
        // next iteration's store targets buf^1, whose last readers finished
        // before the barrier this iteration.
    }

#pragma unroll
    for (int i = 0; i < 8; i++) {
        const int r = row0 + tm * 8 + i;
#pragma unroll
        for (int j4 = 0; j4 < 2; j4++) {
            const int c = col0 + tn * 8 + j4 * 4;
            const float4 bv = *(const float4*)(bias + c);
            float4 o;
            o.x = acc[i][j4 * 4 + 0] + bv.x;
            o.y = acc[i][j4 * 4 + 1] + bv.y;
            o.z = acc[i][j4 * 4 + 2] + bv.z;
            o.w = acc[i][j4 * 4 + 3] + bv.w;
            *(float4*)(C + (size_t)r * EMB + c) = o;
        }
    }
}

// ---------------------------------------------------------------------------
// Flash attention, fp32. One block = (batch b, head h, 64 query rows).
// Q/K stored [d][row] in smem with XOR swizzle (phys col group = (row>>2)^(d>>2))
// so both GEMM stages read conflict-free LDS.128.
// scores = (q . k) * 8  (reference multiplies by sqrt(d))
// ---------------------------------------------------------------------------
__global__ __launch_bounds__(256) void flash_kernel(
    const float* __restrict__ Q, const float* __restrict__ K,
    const float* __restrict__ V, float* __restrict__ O)
{
    extern __shared__ float smem[];
    float (*Qt)[64] = (float(*)[64])(smem);             // [d][i] swizzled
    float (*Kt)[64] = (float(*)[64])(smem + 64 * 64);   // [d][j] swizzled
    float (*Vs)[64] = (float(*)[64])(smem + 2 * 64 * 64); // [j][d] natural
    float (*Pt)[64] = (float(*)[64])(smem + 3 * 64 * 64); // [j][i] swizzled

    const int t  = threadIdx.x;
    const int tm = t >> 4;   // 0..15: owns rows i = tm*4..tm*4+3
    const int tn = t & 15;   // 0..15: owns cols j (or d) = tn*4..tn*4+3
    const int qt = blockIdx.x;
    const int h  = blockIdx.y;
    const int b  = blockIdx.z;
    const size_t base = (size_t)b * SEQ * EMB + (size_t)h * HDIM;

    // load Q tile (64 rows x 64 d), transpose + swizzle into Qt
#pragma unroll
    for (int i = 0; i < 4; i++) {
        const int f  = t + i * 256;
        const int r  = f >> 4;
        const int c4 = f & 15;
        const float4 v = *(const float4*)(Q + base + (size_t)(qt * 64 + r) * EMB + c4 * 4);
        const int pc = ((((r >> 2) ^ c4) & 15) << 2) | (r & 3);
        Qt[c4 * 4 + 0][pc] = v.x;
        Qt[c4 * 4 + 1][pc] = v.y;
        Qt[c4 * 4 + 2][pc] = v.z;
        Qt[c4 * 4 + 3][pc] = v.w;
    }

    float m_i[4], l_i[4], acc[4][4];
#pragma unroll
    for (int i = 0; i < 4; i++) {
        m_i[i] = -1e30f;
        l_i[i] = 0.f;
#pragma unroll
        for (int j = 0; j < 4; j++) acc[i][j] = 0.f;
    }

    for (int kt = 0; kt < SEQ / 64; kt++) {
        __syncthreads();   // protect Kt/Vs/Pt from previous iteration readers
#pragma unroll
        for (int i = 0; i < 4; i++) {
            const int f  = t + i * 256;
            const int r  = f >> 4;
            const int c4 = f & 15;
            const size_t g = base + (size_t)(kt * 64 + r) * EMB + c4 * 4;
            const float4 kv = *(const float4*)(K + g);
            const int pc = ((((r >> 2) ^ c4) & 15) << 2) | (r & 3);
            Kt[c4 * 4 + 0][pc] = kv.x;
            Kt[c4 * 4 + 1][pc] = kv.y;
            Kt[c4 * 4 + 2][pc] = kv.z;
            Kt[c4 * 4 + 3][pc] = kv.w;
            *(float4*)&Vs[r][c4 * 4] = *(const float4*)(V + g);
        }
        __syncthreads();

        // S = Q K^T for this 64x64 tile
        float s[4][4];
#pragma unroll
        for (int i = 0; i < 4; i++)
#pragma unroll
            for (int j = 0; j < 4; j++) s[i][j] = 0.f;

#pragma unroll 16
        for (int d = 0; d < HDIM; d++) {
            const int dg = d >> 2;
            const float4 qv = *(const float4*)&Qt[d][(tm ^ dg) << 2];
            const float4 kv = *(const float4*)&Kt[d][(tn ^ dg) << 2];
            const float qa[4] = {qv.x, qv.y, qv.z, qv.w};
            const float ka[4] = {kv.x, kv.y, kv.z, kv.w};
#pragma unroll
            for (int i = 0; i < 4; i++)
#pragma unroll
                for (int j = 0; j < 4; j++)
                    s[i][j] += qa[i] * ka[j];
        }

        // online softmax (reference scale: multiply by sqrt(64) = 8)
#pragma unroll
        for (int i = 0; i < 4; i++) {
#pragma unroll
            for (int j = 0; j < 4; j++) s[i][j] *= 8.f;

            float mt = fmaxf(fmaxf(s[i][0], s[i][1]), fmaxf(s[i][2], s[i][3]));
#pragma unroll
            for (int off = 1; off < 16; off <<= 1)
                mt = fmaxf(mt, __shfl_xor_sync(0xffffffffu, mt, off));

            const float mnew = fmaxf(m_i[i], mt);
            const float corr = __expf(m_i[i] - mnew);
            m_i[i] = mnew;

            float p[4], rs = 0.f;
#pragma unroll
            for (int j = 0; j < 4; j++) {
                p[j] = __expf(s[i][j] - mnew);
                rs += p[j];
            }
#pragma unroll
            for (int off = 1; off < 16; off <<= 1)
                rs += __shfl_xor_sync(0xffffffffu, rs, off);

            l_i[i] = l_i[i] * corr + rs;
#pragma unroll
            for (int j = 0; j < 4; j++) acc[i][j] *= corr;

            // store P transposed+swizzled: Pt[j][i_global], phys col = (tm^tn)*4 + i
            const int pc = ((tm ^ tn) << 2) | i;
#pragma unroll
            for (int j = 0; j < 4; j++) Pt[tn * 4 + j][pc] = p[j];
        }
        __syncthreads();

        // O += P V  (thread owns rows i=tm*4.., dims d=tn*4..)
#pragma unroll 8
        for (int j = 0; j < 64; j++) {
            const float4 pv = *(const float4*)&Pt[j][(tm ^ (j >> 2)) << 2];
            const float4 vv = *(const float4*)&Vs[j][tn * 4];
            const float pa[4] = {pv.x, pv.y, pv.z, pv.w};
            const float va[4] = {vv.x, vv.y, vv.z, vv.w};
#pragma unroll
            for (int i = 0; i < 4; i++)
#pragma unroll
                for (int c = 0; c < 4; c++)
                    acc[i][c] += pa[i] * va[c];
        }
    }

    // epilogue: divide by l, write out in [b, s, h*D+d] layout
#pragma unroll
    for (int i = 0; i < 4; i++) {
        const float inv = 1.f / l_i[i];
        float4 o;
        o.x = acc[i][0] * inv;
        o.y = acc[i][1] * inv;
        o.z = acc[i][2] * inv;
        o.w = acc[i][3] * inv;
        *(float4*)(O + base + (size_t)(qt * 64 + tm * 4 + i) * EMB + tn * 4) = o;
    }
}

// ---------------------------------------------------------------------------
extern "C" void kernel_launch(void* const* d_in, const int* in_sizes, int n_in,
                              void* d_out, int out_size)
{
    const float* x  = (const float*)d_in[0];
    const float* Wq = (const float*)d_in[1];
    const float* bq = (const float*)d_in[2];
    const float* Wk = (const float*)d_in[3];
    const float* bk = (const float*)d_in[4];
    const float* Wv = (const float*)d_in[5];
    const float* bv = (const float*)d_in[6];
    const float* Wo = (const float*)d_in[7];
    const float* bo = (const float*)d_in[8];
    float* out = (float*)d_out;

    static float *Qp = nullptr, *Kp = nullptr, *Vp = nullptr, *Ap = nullptr;
    if (!Qp) {
        cudaGetSymbolAddress((void**)&Qp, g_Q);
        cudaGetSymbolAddress((void**)&Kp, g_K);
        cudaGetSymbolAddress((void**)&Vp, g_V);
        cudaGetSymbolAddress((void**)&Ap, g_A);
        cudaFuncSetAttribute(flash_kernel,
                             cudaFuncAttributeMaxDynamicSharedMemorySize,
                             4 * 64 * 64 * (int)sizeof(float));
    }

    const dim3 gg(EMB / 128, ROWS / 128);
    gemm_bias_kernel<<<gg, 256>>>(x, Wq, bq, Qp);
    gemm_bias_kernel<<<gg, 256>>>(x, Wk, bk, Kp);
    gemm_bias_kernel<<<gg, 256>>>(x, Wv, bv, Vp);

    const size_t smem = 4 * 64 * 64 * sizeof(float);
    flash_kernel<<<dim3(SEQ / 64, NHEAD, BATCH), 256, smem>>>(Qp, Kp, Vp, Ap);

    gemm_bias_kernel<<<gg, 256>>>(Ap, Wo, bo, out);
}

// round 9
// speedup vs baseline: 1.4805x; 1.4803x over previous
#include <cuda_runtime.h>
#include <cuda_bf16.h>
#include <cstdint>
#include <math.h>

#define SEQ   2048
#define BATCH 4
#define EMB   1024
#define NHEAD 16
#define HDIM  64
#define ROWS  (BATCH * SEQ)

// ---------------- scratch (allocation-free contract) ----------------
__device__ float g_Q[ROWS * EMB];
__device__ float g_K[ROWS * EMB];
__device__ float g_V[ROWS * EMB];
__device__ float g_A[ROWS * EMB];
__device__ __nv_bfloat16 g_xh[ROWS * EMB], g_xl[ROWS * EMB];
__device__ __nv_bfloat16 g_ah[ROWS * EMB], g_al[ROWS * EMB];
__device__ __nv_bfloat16 g_Wth[4 * EMB * EMB], g_Wtl[4 * EMB * EMB];

#define SW128(x) ((x) ^ (((x) >> 3) & 0x70))

// ---------------- PTX helpers (plain sm_103-safe: no tcgen05) ----------------
__device__ __forceinline__ uint32_t smem_u32(const void* p) {
    uint32_t a;
    asm("{ .reg .u64 t; cvta.to.shared.u64 t, %1; cvt.u32.u64 %0, t; }" : "=r"(a) : "l"(p));
    return a;
}
__device__ __forceinline__ void cpa16(uint32_t dst, const void* src) {
    asm volatile("cp.async.cg.shared.global [%0], [%1], 16;" :: "r"(dst), "l"(src));
}
__device__ __forceinline__ void cpa_commit() { asm volatile("cp.async.commit_group;"); }
__device__ __forceinline__ void cpa_wait0()  { asm volatile("cp.async.wait_group 0;"); }
__device__ __forceinline__ void cpa_wait1()  { asm volatile("cp.async.wait_group 1;"); }

__device__ __forceinline__ void ldm_x4(uint32_t& r0, uint32_t& r1, uint32_t& r2,
                                       uint32_t& r3, uint32_t addr) {
    asm volatile("ldmatrix.sync.aligned.m8n8.x4.shared.b16 {%0,%1,%2,%3}, [%4];"
                 : "=r"(r0), "=r"(r1), "=r"(r2), "=r"(r3) : "r"(addr));
}
__device__ __forceinline__ void mma_bf16(float* d, const uint32_t* a, const uint32_t* b,
                                         const float* c) {
    asm volatile("mma.sync.aligned.m16n8k16.row.col.f32.bf16.bf16.f32 "
                 "{%0,%1,%2,%3}, {%4,%5,%6,%7}, {%8,%9}, {%10,%11,%12,%13};"
                 : "=f"(d[0]), "=f"(d[1]), "=f"(d[2]), "=f"(d[3])
                 : "r"(a[0]), "r"(a[1]), "r"(a[2]), "r"(a[3]),
                   "r"(b[0]), "r"(b[1]),
                   "f"(c[0]), "f"(c[1]), "f"(c[2]), "f"(c[3]));
}

// ---------------------------------------------------------------------------
// split fp32 -> (bf16 hi, bf16 lo)
// ---------------------------------------------------------------------------
__global__ __launch_bounds__(256) void split_kernel(
    const float* __restrict__ X, __nv_bfloat16* __restrict__ H,
    __nv_bfloat16* __restrict__ L)
{
    const int i = (blockIdx.x * 256 + threadIdx.x) * 4;
    const float4 v = *(const float4*)(X + i);
    const float a[4] = {v.x, v.y, v.z, v.w};
    __nv_bfloat16 h[4], l[4];
#pragma unroll
    for (int j = 0; j < 4; j++) {
        h[j] = __float2bfloat16(a[j]);
        l[j] = __float2bfloat16(a[j] - __bfloat162float(h[j]));
    }
    *(uint2*)(H + i) = *(uint2*)h;
    *(uint2*)(L + i) = *(uint2*)l;
}

// ---------------------------------------------------------------------------
// transpose + split: Wt[n][k] = W[k][n], output split bf16 hi/lo
// ---------------------------------------------------------------------------
__global__ __launch_bounds__(256) void wsplit_kernel(
    const float* __restrict__ W, __nv_bfloat16* __restrict__ Th,
    __nv_bfloat16* __restrict__ Tl)
{
    __shared__ float s[32][33];
    const int bx = blockIdx.x * 32;   // n base
    const int by = blockIdx.y * 32;   // k base
    const int tx = threadIdx.x & 31;
    const int ty0 = threadIdx.x >> 5; // 0..7
#pragma unroll
    for (int i = 0; i < 4; i++) {
        const int ty = ty0 + i * 8;
        s[ty][tx] = W[(size_t)(by + ty) * EMB + bx + tx];
    }
    __syncthreads();
#pragma unroll
    for (int i = 0; i < 4; i++) {
        const int ty = ty0 + i * 8;       // n offset
        const float v = s[tx][ty];        // = W[by+tx][bx+ty]
        const __nv_bfloat16 h = __float2bfloat16(v);
        const __nv_bfloat16 l = __float2bfloat16(v - __bfloat162float(h));
        const size_t o = (size_t)(bx + ty) * EMB + by + tx;
        Th[o] = h;
        Tl[o] = l;
    }
}

// ---------------------------------------------------------------------------
// mma.sync split-bf16 GEMM: C[M,N] = A[M,K] @ B[N,K]^T + bias
// C = Ah*Bh + Ah*Bl + Al*Bh, fp32 accumulate in registers.
// 128x128 CTA tile, 8 warps (2m x 4n), warp tile 64x32.
// K-stage 64 bf16, 4 smem tiles (Ah,Al,Bh,Bl) of 128x64 each, SW128 swizzled,
// double-buffered cp.async.
// ---------------------------------------------------------------------------
#define GS_BUF   65536                 // one buffer: 4 tiles x 16KB
#define GS_TOTAL (2 * GS_BUF)          // 131072

__global__ __launch_bounds__(256) void tc_gemm(
    const __nv_bfloat16* __restrict__ Ah, const __nv_bfloat16* __restrict__ Al,
    const __nv_bfloat16* __restrict__ Bh, const __nv_bfloat16* __restrict__ Bl,
    const float* __restrict__ bias, float* __restrict__ C)
{
    extern __shared__ char smem[];
    const uint32_t sb = smem_u32(smem);
    const int tid  = threadIdx.x;
    const int wid  = tid >> 5;
    const int lane = tid & 31;
    const int wm   = wid >> 2;        // 0..1  (m direction, 64 rows each)
    const int wn   = wid & 3;         // 0..3  (n direction, 32 cols each)
    const int row0 = blockIdx.y * 128;
    const int col0 = blockIdx.x * 128;

    const __nv_bfloat16* gsrc[4] = {Ah, Al, Bh, Bl};

    // per-thread load assignment (16 cp.asyncs per thread per stage)
    auto load_chunk = [&](int kc, int buf) {
        const uint32_t bofs = (uint32_t)buf * GS_BUF;
#pragma unroll
        for (int it = 0; it < 16; it++) {
            const int id  = tid + it * 256;
            const int t   = id >> 10;          // tile 0..3
            const int rem = id & 1023;
            const int r   = rem >> 3;          // row 0..127
            const int c   = rem & 7;           // 16B chunk 0..7
            const int grow = (t < 2 ? row0 : col0) + r;
            const __nv_bfloat16* g = gsrc[t] + (size_t)grow * EMB + kc * 64 + c * 8;
            cpa16(sb + bofs + t * 16384 + SW128(r * 128 + c * 16), g);
        }
        cpa_commit();
    };

    float acc[4][4][4];
#pragma unroll
    for (int mt = 0; mt < 4; mt++)
#pragma unroll
        for (int nt = 0; nt < 4; nt++)
#pragma unroll
            for (int j = 0; j < 4; j++) acc[mt][nt][j] = 0.f;

    // fragment address components (canonical ldmatrix lane mapping)
    const int arow = wm * 64 + (lane & 15);            // + mt*16
    const int akb  = (lane >> 4) << 3;                 // 0 or 8 (k half)
    const int brow = ((lane >> 4) << 3) + (lane & 7);  // n within 16-wide pair
    const int bkb  = ((lane >> 3) & 1) << 3;           // 0 or 8 (k half)

    load_chunk(0, 0);

    for (int kc = 0; kc < 16; kc++) {
        if (kc < 15) { load_chunk(kc + 1, (kc + 1) & 1); cpa_wait1(); }
        else         { cpa_wait0(); }
        __syncthreads();

        const uint32_t bofs = sb + (uint32_t)(kc & 1) * GS_BUF;

#pragma unroll
        for (int ks = 0; ks < 4; ks++) {
            const int k0 = ks * 16;
            uint32_t ahf[4][4], alf[4][4], bhf[2][4], blf[2][4];

#pragma unroll
            for (int mt = 0; mt < 4; mt++) {
                const uint32_t off = SW128((arow + mt * 16) * 128 + (k0 + akb) * 2);
                ldm_x4(ahf[mt][0], ahf[mt][1], ahf[mt][2], ahf[mt][3],
                       bofs + 0 * 16384 + off);
            }
#pragma unroll
            for (int np = 0; np < 2; np++) {
                const uint32_t off = SW128((wn * 32 + np * 16 + brow) * 128 + (k0 + bkb) * 2);
                ldm_x4(bhf[np][0], bhf[np][1], bhf[np][2], bhf[np][3],
                       bofs + 2 * 16384 + off);
            }
            // hh
#pragma unroll
            for (int mt = 0; mt < 4; mt++)
#pragma unroll
                for (int nt = 0; nt < 4; nt++)
                    mma_bf16(acc[mt][nt], ahf[mt], &bhf[nt >> 1][(nt & 1) * 2], acc[mt][nt]);

#pragma unroll
            for (int np = 0; np < 2; np++) {
                const uint32_t off = SW128((wn * 32 + np * 16 + brow) * 128 + (k0 + bkb) * 2);
                ldm_x4(blf[np][0], blf[np][1], blf[np][2], blf[np][3],
                       bofs + 3 * 16384 + off);
            }
            // hl
#pragma unroll
            for (int mt = 0; mt < 4; mt++)
#pragma unroll
                for (int nt = 0; nt < 4; nt++)
                    mma_bf16(acc[mt][nt], ahf[mt], &blf[nt >> 1][(nt & 1) * 2], acc[mt][nt]);

#pragma unroll
            for (int mt = 0; mt < 4; mt++) {
                const uint32_t off = SW128((arow + mt * 16) * 128 + (k0 + akb) * 2);
                ldm_x4(alf[mt][0], alf[mt][1], alf[mt][2], alf[mt][3],
                       bofs + 1 * 16384 + off);
            }
            // lh
#pragma unroll
            for (int mt = 0; mt < 4; mt++)
#pragma unroll
                for (int nt = 0; nt < 4; nt++)
                    mma_bf16(acc[mt][nt], alf[mt], &bhf[nt >> 1][(nt & 1) * 2], acc[mt][nt]);
        }
        __syncthreads();
    }

    // epilogue: add bias, store fp32
    const int qr = lane >> 2;         // 0..7
    const int qc = (lane & 3) * 2;    // 0,2,4,6
#pragma unroll
    for (int mt = 0; mt < 4; mt++) {
#pragma unroll
        for (int nt = 0; nt < 4; nt++) {
            const int gm = row0 + wm * 64 + mt * 16 + qr;
            const int gn = col0 + wn * 32 + nt * 8 + qc;
            const float b0 = bias[gn], b1 = bias[gn + 1];
            float2 v0, v1;
            v0.x = acc[mt][nt][0] + b0; v0.y = acc[mt][nt][1] + b1;
            v1.x = acc[mt][nt][2] + b0; v1.y = acc[mt][nt][3] + b1;
            *(float2*)(C + (size_t)gm * EMB + gn)       = v0;
            *(float2*)(C + (size_t)(gm + 8) * EMB + gn) = v1;
        }
    }
}

// ---------------------------------------------------------------------------
// Flash attention, fp32 (unchanged — known good)
// ---------------------------------------------------------------------------
__global__ __launch_bounds__(256) void flash_kernel(
    const float* __restrict__ Q, const float* __restrict__ K,
    const float* __restrict__ V, float* __restrict__ O)
{
    extern __shared__ float fsm[];
    float (*Qt)[64] = (float(*)[64])(fsm);
    float (*Kt)[64] = (float(*)[64])(fsm + 64 * 64);
    float (*Vs)[64] = (float(*)[64])(fsm + 2 * 64 * 64);
    float (*Pt)[64] = (float(*)[64])(fsm + 3 * 64 * 64);

    const int t  = threadIdx.x;
    const int tm = t >> 4;
    const int tn = t & 15;
    const int qt = blockIdx.x;
    const int h  = blockIdx.y;
    const int b  = blockIdx.z;
    const size_t base = (size_t)b * SEQ * EMB + (size_t)h * HDIM;

#pragma unroll
    for (int i = 0; i < 4; i++) {
        const int f  = t + i * 256;
        const int r  = f >> 4;
        const int c4 = f & 15;
        const float4 v = *(const float4*)(Q + base + (size_t)(qt * 64 + r) * EMB + c4 * 4);
        const int pc = ((((r >> 2) ^ c4) & 15) << 2) | (r & 3);
        Qt[c4 * 4 + 0][pc] = v.x;
        Qt[c4 * 4 + 1][pc] = v.y;
        Qt[c4 * 4 + 2][pc] = v.z;
        Qt[c4 * 4 + 3][pc] = v.w;
    }

    float m_i[4], l_i[4], acc[4][4];
#pragma unroll
    for (int i = 0; i < 4; i++) {
        m_i[i] = -1e30f;
        l_i[i] = 0.f;
#pragma unroll
        for (int j = 0; j < 4; j++) acc[i][j] = 0.f;
    }

    for (int kt = 0; kt < SEQ / 64; kt++) {
        __syncthreads();
#pragma unroll
        for (int i = 0; i < 4; i++) {
            const int f  = t + i * 256;
            const int r  = f >> 4;
            const int c4 = f & 15;
            const size_t g = base + (size_t)(kt * 64 + r) * EMB + c4 * 4;
            const float4 kv = *(const float4*)(K + g);
            const int pc = ((((r >> 2) ^ c4) & 15) << 2) | (r & 3);
            Kt[c4 * 4 + 0][pc] = kv.x;
            Kt[c4 * 4 + 1][pc] = kv.y;
            Kt[c4 * 4 + 2][pc] = kv.z;
            Kt[c4 * 4 + 3][pc] = kv.w;
            *(float4*)&Vs[r][c4 * 4] = *(const float4*)(V + g);
        }
        __syncthreads();

        float s[4][4];
#pragma unroll
        for (int i = 0; i < 4; i++)
#pragma unroll
            for (int j = 0; j < 4; j++) s[i][j] = 0.f;

#pragma unroll 16
        for (int d = 0; d < HDIM; d++) {
            const int dg = d >> 2;
            const float4 qv = *(const float4*)&Qt[d][(tm ^ dg) << 2];
            const float4 kv = *(const float4*)&Kt[d][(tn ^ dg) << 2];
            const float qa[4] = {qv.x, qv.y, qv.z, qv.w};
            const float ka[4] = {kv.x, kv.y, kv.z, kv.w};
#pragma unroll
            for (int i = 0; i < 4; i++)
#pragma unroll
                for (int j = 0; j < 4; j++)
                    s[i][j] += qa[i] * ka[j];
        }

#pragma unroll
        for (int i = 0; i < 4; i++) {
#pragma unroll
            for (int j = 0; j < 4; j++) s[i][j] *= 8.f;

            float mt = fmaxf(fmaxf(s[i][0], s[i][1]), fmaxf(s[i][2], s[i][3]));
#pragma unroll
            for (int off = 1; off < 16; off <<= 1)
                mt = fmaxf(mt, __shfl_xor_sync(0xffffffffu, mt, off));

            const float mnew = fmaxf(m_i[i], mt);
            const float corr = __expf(m_i[i] - mnew);
            m_i[i] = mnew;

            float p[4], rs = 0.f;
#pragma unroll
            for (int j = 0; j < 4; j++) {
                p[j] = __expf(s[i][j] - mnew);
                rs += p[j];
            }
#pragma unroll
            for (int off = 1; off < 16; off <<= 1)
                rs += __shfl_xor_sync(0xffffffffu, rs, off);

            l_i[i] = l_i[i] * corr + rs;
#pragma unroll
            for (int j = 0; j < 4; j++) acc[i][j] *= corr;

            const int pc = ((tm ^ tn) << 2) | i;
#pragma unroll
            for (int j = 0; j < 4; j++) Pt[tn * 4 + j][pc] = p[j];
        }
        __syncthreads();

#pragma unroll 8
        for (int j = 0; j < 64; j++) {
            const float4 pv = *(const float4*)&Pt[j][(tm ^ (j >> 2)) << 2];
            const float4 vv = *(const float4*)&Vs[j][tn * 4];
            const float pa[4] = {pv.x, pv.y, pv.z, pv.w};
            const float va[4] = {vv.x, vv.y, vv.z, vv.w};
#pragma unroll
            for (int i = 0; i < 4; i++)
#pragma unroll
                for (int c = 0; c < 4; c++)
                    acc[i][c] += pa[i] * va[c];
        }
    }

#pragma unroll
    for (int i = 0; i < 4; i++) {
        const float inv = 1.f / l_i[i];
        float4 o;
        o.x = acc[i][0] * inv;
        o.y = acc[i][1] * inv;
        o.z = acc[i][2] * inv;
        o.w = acc[i][3] * inv;
        *(float4*)(O + base + (size_t)(qt * 64 + tm * 4 + i) * EMB + tn * 4) = o;
    }
}

// ---------------------------------------------------------------------------
extern "C" void kernel_launch(void* const* d_in, const int* in_sizes, int n_in,
                              void* d_out, int out_size)
{
    const float* x  = (const float*)d_in[0];
    const float* Wq = (const float*)d_in[1];
    const float* bq = (const float*)d_in[2];
    const float* Wk = (const float*)d_in[3];
    const float* bk = (const float*)d_in[4];
    const float* Wv = (const float*)d_in[5];
    const float* bv = (const float*)d_in[6];
    const float* Wo = (const float*)d_in[7];
    const float* bo = (const float*)d_in[8];
    float* out = (float*)d_out;

    static float *Qp, *Kp, *Vp, *Ap;
    static __nv_bfloat16 *xh, *xl, *ah, *al, *Wth, *Wtl;
    static bool init = false;
    if (!init) {
        init = true;
        cudaGetSymbolAddress((void**)&Qp, g_Q);
        cudaGetSymbolAddress((void**)&Kp, g_K);
        cudaGetSymbolAddress((void**)&Vp, g_V);
        cudaGetSymbolAddress((void**)&Ap, g_A);
        cudaGetSymbolAddress((void**)&xh, g_xh);
        cudaGetSymbolAddress((void**)&xl, g_xl);
        cudaGetSymbolAddress((void**)&ah, g_ah);
        cudaGetSymbolAddress((void**)&al, g_al);
        cudaGetSymbolAddress((void**)&Wth, g_Wth);
        cudaGetSymbolAddress((void**)&Wtl, g_Wtl);
        cudaFuncSetAttribute(flash_kernel,
                             cudaFuncAttributeMaxDynamicSharedMemorySize,
                             4 * 64 * 64 * (int)sizeof(float));
        cudaFuncSetAttribute(tc_gemm,
                             cudaFuncAttributeMaxDynamicSharedMemorySize, GS_TOTAL);
    }

    const int WS = EMB * EMB;

    // conversions
    split_kernel<<<ROWS * EMB / 1024, 256>>>(x, xh, xl);
    const dim3 wg(EMB / 32, EMB / 32);
    wsplit_kernel<<<wg, 256>>>(Wq, Wth + 0 * WS, Wtl + 0 * WS);
    wsplit_kernel<<<wg, 256>>>(Wk, Wth + 1 * WS, Wtl + 1 * WS);
    wsplit_kernel<<<wg, 256>>>(Wv, Wth + 2 * WS, Wtl + 2 * WS);
    wsplit_kernel<<<wg, 256>>>(Wo, Wth + 3 * WS, Wtl + 3 * WS);

    // Q, K, V projections on tensor cores (mma.sync)
    const dim3 gg(EMB / 128, ROWS / 128);
    tc_gemm<<<gg, 256, GS_TOTAL>>>(xh, xl, Wth + 0 * WS, Wtl + 0 * WS, bq, Qp);
    tc_gemm<<<gg, 256, GS_TOTAL>>>(xh, xl, Wth + 1 * WS, Wtl + 1 * WS, bk, Kp);
    tc_gemm<<<gg, 256, GS_TOTAL>>>(xh, xl, Wth + 2 * WS, Wtl + 2 * WS, bv, Vp);

    // attention (fp32 flash)
    const size_t smem = 4 * 64 * 64 * sizeof(float);
    flash_kernel<<<dim3(SEQ / 64, NHEAD, BATCH), 256, smem>>>(Qp, Kp, Vp, Ap);

    // output projection
    split_kernel<<<ROWS * EMB / 1024, 256>>>(Ap, ah, al);
    tc_gemm<<<gg, 256, GS_TOTAL>>>(ah, al, Wth + 3 * WS, Wtl + 3 * WS, bo, out);
}